// round 10
// baseline (speedup 1.0000x reference)
#include <cuda_runtime.h>
#include <math.h>

#define N_IN        1024
#define N_OUT       4096
#define BATCH       8
#define OC          64
#define THREADS     1024
#define M_PER_BLOCK 256
#define NSUB        4                      // threads cooperating per target

#define GRID        13
#define NCELL       (GRID * GRID)          // 169
#define INV_CELL    (GRID / 4.0f)          // 3.25
#define CAP         12                     // bucket capacity per cell
#define OVF_MAX     128                    // overflow side-list capacity
// natural-log cutoff: terms with exponent < -T are dropped.
// T=45 -> e^-45 ~ 3e-20; with the reference's +1e-8 denominator guard this is
// ~1e-8 absolute error worst case. Far below the 1e-3 rel_err gate.
#define CUTOFF_T    45.0f

__device__ __forceinline__ float ex2_approx(float x) {
    float r;
    asm("ex2.approx.ftz.f32 %0, %1;" : "=f"(r) : "f"(x));
    return r;
}

__device__ __forceinline__ int cell_of(float v) {
    int c = (int)((v + 2.0f) * INV_CELL);
    return min(GRID - 1, max(0, c));
}

__global__ __launch_bounds__(THREADS, 1)
void conv_deepset_kernel(const float* __restrict__ x,
                         const float* __restrict__ y,
                         const float* __restrict__ t,
                         const float* __restrict__ sigma,
                         const float* __restrict__ W,
                         const float* __restrict__ bias,
                         float* __restrict__ out)
{
    __shared__ float4 bucket[NCELL * CAP];        // 32.4 KB, scaled (sx, sy, yval, -)
    __shared__ float4 ovf[OVF_MAX];               // 2 KB, (sx, sy, yval, cell_id)
    __shared__ int    cnt[NCELL];
    __shared__ int    novf;
    __shared__ float  p0_s[NSUB * M_PER_BLOCK];   // partial acc0 per sub
    __shared__ float  p1_s[NSUB * M_PER_BLOCK];   // partial acc1 per sub
    __shared__ float  dens_s[M_PER_BLOCK];
    __shared__ float  q_s[M_PER_BLOCK];
    __shared__ float  Ws[2 * OC];
    __shared__ float  bs[OC];

    const int b   = blockIdx.y;
    const int tid = threadIdx.x;

    // ---- kick off independent global loads FIRST (overlap with everything) ----
    const int ml  = tid & (M_PER_BLOCK - 1);     // target index within block
    const int sub = tid >> 8;                    // 0..3, uniform within a warp
    const int m   = blockIdx.x * M_PER_BLOCK + ml;
    const float2 tv  = ((const float2*)(t + (size_t)b * N_OUT * 2))[m];
    const float2 pxv = ((const float2*)(x + (size_t)b * N_IN * 2))[tid];
    const float  pyv = (y + (size_t)b * N_IN)[tid];

    // ---- per-channel constants ----
    const float LOG2E = 1.4426950408889634f;
    const float s0 = expf(sigma[0]);
    const float s1 = expf(sigma[1]);
    // e_k = exp2( -d_scaled * ... ),  scaling coords by u0 = sqrt(0.5*LOG2E)/s0
    const float u0    = sqrtf(0.5f * LOG2E) / s0;
    const float ratio = (s0 * s0) / (s1 * s1);   // d1' = d0' * ratio
    const bool  equal_sig = (s0 == s1);

    // neighborhood half-width in cells, from the *larger* scale
    const float smax = fmaxf(s0, s1);
    const float r_needed = sqrtf(2.0f * CUTOFF_T) * smax;
    int nb = (int)ceilf(r_needed * INV_CELL);
    nb = max(1, min(GRID - 1, nb));

    // ---- phase 0: zero counts, stage W/b ----
    if (tid < NCELL) cnt[tid] = 0;
    if (tid == THREADS - 1) novf = 0;
    if (tid < 2 * OC) Ws[tid] = W[tid];
    else if (tid >= 128 && tid < 128 + OC) bs[tid - 128] = bias[tid - 128];
    __syncthreads();

    // ---- phase 1: single-pass bucket build (1 point / thread) ----
    {
        int c = cell_of(pxv.y) * GRID + cell_of(pxv.x);
        int slot = atomicAdd(&cnt[c], 1);
        float4 p4 = make_float4(pxv.x * u0, pxv.y * u0, pyv, 0.0f);
        if (slot < CAP) {
            bucket[c * CAP + slot] = p4;
        } else {
            int o = atomicAdd(&novf, 1);
            if (o < OVF_MAX) { p4.w = (float)c; ovf[o] = p4; }
        }
    }
    __syncthreads();

    // ---- phase 2: query — NSUB threads cooperate per target ----
    const float stx = tv.x * u0;
    const float sty = tv.y * u0;

    const int cx = cell_of(tv.x);
    const int cy = cell_of(tv.y);
    const int cx0 = max(0, cx - nb), cx1 = min(GRID - 1, cx + nb);
    const int cy0 = max(0, cy - nb), cy1 = min(GRID - 1, cy + nb);

    float acc0 = 0.0f;   // density channel
    float acc1 = 0.0f;   // conv channel
    const int nov = min(novf, OVF_MAX);

    if (equal_sig) {
        for (int ry = cy0; ry <= cy1; ++ry) {
            for (int rx = cx0; rx <= cx1; ++rx) {
                int c  = ry * GRID + rx;
                int n  = min(cnt[c], CAP);
                int bb = c * CAP;
                #pragma unroll 2
                for (int j = sub; j < n; j += NSUB) {
                    float4 p = bucket[bb + j];
                    float dx = p.x - stx;
                    float dy = p.y - sty;
                    float d  = fmaf(dy, dy, dx * dx);
                    float e0 = ex2_approx(-d);
                    acc0 += e0;
                    acc1 = fmaf(p.z, e0, acc1);
                }
            }
        }
        for (int k = sub; k < nov; k += NSUB) {
            float4 p = ovf[k];
            int oc  = (int)p.w;
            int ocy = oc / GRID, ocx = oc - ocy * GRID;
            if (ocx >= cx0 && ocx <= cx1 && ocy >= cy0 && ocy <= cy1) {
                float dx = p.x - stx;
                float dy = p.y - sty;
                float d  = fmaf(dy, dy, dx * dx);
                float e0 = ex2_approx(-d);
                acc0 += e0;
                acc1 = fmaf(p.z, e0, acc1);
            }
        }
    } else {
        for (int ry = cy0; ry <= cy1; ++ry) {
            for (int rx = cx0; rx <= cx1; ++rx) {
                int c  = ry * GRID + rx;
                int n  = min(cnt[c], CAP);
                int bb = c * CAP;
                #pragma unroll 2
                for (int j = sub; j < n; j += NSUB) {
                    float4 p = bucket[bb + j];
                    float dx = p.x - stx;
                    float dy = p.y - sty;
                    float d  = fmaf(dy, dy, dx * dx);
                    float e0 = ex2_approx(-d);
                    float e1 = ex2_approx(-d * ratio);
                    acc0 += e0;
                    acc1 = fmaf(p.z, e1, acc1);
                }
            }
        }
        for (int k = sub; k < nov; k += NSUB) {
            float4 p = ovf[k];
            int oc  = (int)p.w;
            int ocy = oc / GRID, ocx = oc - ocy * GRID;
            if (ocx >= cx0 && ocx <= cx1 && ocy >= cy0 && ocy <= cy1) {
                float dx = p.x - stx;
                float dy = p.y - sty;
                float d  = fmaf(dy, dy, dx * dx);
                float e0 = ex2_approx(-d);
                float e1 = ex2_approx(-d * ratio);
                acc0 += e0;
                acc1 = fmaf(p.z, e1, acc1);
            }
        }
    }

    p0_s[sub * M_PER_BLOCK + ml] = acc0;
    p1_s[sub * M_PER_BLOCK + ml] = acc1;
    __syncthreads();

    // ---- phase 3: reduce partials (first 256 threads) ----
    if (tid < M_PER_BLOCK) {
        float a0 = p0_s[tid] + p0_s[M_PER_BLOCK + tid]
                 + p0_s[2 * M_PER_BLOCK + tid] + p0_s[3 * M_PER_BLOCK + tid];
        float a1 = p1_s[tid] + p1_s[M_PER_BLOCK + tid]
                 + p1_s[2 * M_PER_BLOCK + tid] + p1_s[3 * M_PER_BLOCK + tid];
        dens_s[tid] = a0;
        q_s[tid]    = a1 / (a0 + 1e-8f);
    }
    __syncthreads();

    // ---- phase 4: epilogue: out[b, m, o] = dens*W[o,0] + q*W[o,1] + b[o] ----
    float4* __restrict__ ob =
        (float4*)(out + ((size_t)b * N_OUT + (size_t)blockIdx.x * M_PER_BLOCK) * OC);

    #pragma unroll
    for (int i = tid; i < M_PER_BLOCK * OC / 4; i += THREADS) {
        int m_local = i >> 4;          // 16 float4 per m-row
        int o0      = (i & 15) * 4;
        float f0 = dens_s[m_local];
        float f1 = q_s[m_local];
        float4 v;
        v.x = fmaf(f0, Ws[(o0 + 0) * 2], fmaf(f1, Ws[(o0 + 0) * 2 + 1], bs[o0 + 0]));
        v.y = fmaf(f0, Ws[(o0 + 1) * 2], fmaf(f1, Ws[(o0 + 1) * 2 + 1], bs[o0 + 1]));
        v.z = fmaf(f0, Ws[(o0 + 2) * 2], fmaf(f1, Ws[(o0 + 2) * 2 + 1], bs[o0 + 2]));
        v.w = fmaf(f0, Ws[(o0 + 3) * 2], fmaf(f1, Ws[(o0 + 3) * 2 + 1], bs[o0 + 3]));
        ob[i] = v;
    }
}

extern "C" void kernel_launch(void* const* d_in, const int* in_sizes, int n_in,
                              void* d_out, int out_size)
{
    const float* x     = (const float*)d_in[0];
    const float* y     = (const float*)d_in[1];
    const float* t     = (const float*)d_in[2];
    const float* sigma = (const float*)d_in[3];
    const float* W     = (const float*)d_in[4];
    const float* bias  = (const float*)d_in[5];
    float* out = (float*)d_out;

    dim3 grid(N_OUT / M_PER_BLOCK, BATCH);   // 16 x 8 = 128 blocks, single wave
    conv_deepset_kernel<<<grid, THREADS>>>(x, y, t, sigma, W, bias, out);
}

// round 11
// speedup vs baseline: 1.2653x; 1.2653x over previous
#include <cuda_runtime.h>
#include <math.h>

#define N_IN        1024
#define N_OUT       4096
#define BATCH       8
#define OC          64
#define THREADS     1024
#define M_PER_BLOCK 256
#define NSUB        4                      // lanes cooperating per target (within warp)

#define GRID        13
#define NCELL       (GRID * GRID)          // 169
#define INV_CELL    (GRID / 4.0f)          // 3.25
// natural-log cutoff: terms with exponent < -T are dropped.
// T=45 -> e^-45 ~ 3e-20; with the reference's +1e-8 denominator guard this is
// ~1e-8 absolute error worst case. Far below the 1e-3 rel_err gate.
#define CUTOFF_T    45.0f

__device__ __forceinline__ float ex2_approx(float x) {
    float r;
    asm("ex2.approx.ftz.f32 %0, %1;" : "=f"(r) : "f"(x));
    return r;
}

__device__ __forceinline__ int cell_of(float v) {
    int c = (int)((v + 2.0f) * INV_CELL);
    return min(GRID - 1, max(0, c));
}

__global__ __launch_bounds__(THREADS, 1)
void conv_deepset_kernel(const float* __restrict__ x,
                         const float* __restrict__ y,
                         const float* __restrict__ t,
                         const float* __restrict__ sigma,
                         const float* __restrict__ W,
                         const float* __restrict__ bias,
                         float* __restrict__ out)
{
    __shared__ float4 pts[N_IN];              // scaled (sx, sy, yval, pad), sorted by cell
    __shared__ int    cnt[NCELL];
    __shared__ int    start[NCELL + 1];
    __shared__ int    ofs[NCELL];
    __shared__ float  dens_s[M_PER_BLOCK];
    __shared__ float  q_s[M_PER_BLOCK];
    __shared__ float  Ws[2 * OC];
    __shared__ float  bs[OC];

    const int b   = blockIdx.y;
    const int tid = threadIdx.x;

    // target mapping: tid = 32*w + 4*g + sub  ->  ml = 8*w + g = tid>>2, sub = tid&3
    const int ml  = tid >> 2;
    const int sub = tid & (NSUB - 1);
    const int m   = blockIdx.x * M_PER_BLOCK + ml;

    // ---- kick off independent global loads FIRST (overlap with everything) ----
    const float2 tv  = ((const float2*)(t + (size_t)b * N_OUT * 2))[m];
    const float2 pxv = ((const float2*)(x + (size_t)b * N_IN * 2))[tid];
    const float  pyv = (y + (size_t)b * N_IN)[tid];

    // ---- per-channel constants ----
    const float LOG2E = 1.4426950408889634f;
    const float s0 = expf(sigma[0]);
    const float s1 = expf(sigma[1]);
    // scale coords by u0 so e0 = exp2(-d_scaled)
    const float u0    = sqrtf(0.5f * LOG2E) / s0;
    const float ratio = (s0 * s0) / (s1 * s1);   // d1' = d0' * ratio
    const bool  equal_sig = (s0 == s1);

    // neighborhood half-width in cells, from the *larger* scale
    const float smax = fmaxf(s0, s1);
    const float r_needed = sqrtf(2.0f * CUTOFF_T) * smax;
    int nb = (int)ceilf(r_needed * INV_CELL);
    nb = max(1, min(GRID - 1, nb));

    // ---- phase 0: zero counts, stage W/b ----
    if (tid < NCELL) cnt[tid] = 0;
    if (tid < 2 * OC) Ws[tid] = W[tid];
    else if (tid >= 128 && tid < 128 + OC) bs[tid - 128] = bias[tid - 128];
    __syncthreads();

    // ---- phase 1: count cells (1 point / thread) ----
    const int pcell = cell_of(pxv.y) * GRID + cell_of(pxv.x);
    atomicAdd(&cnt[pcell], 1);
    __syncthreads();

    // ---- phase 2: exclusive scan over 169 cells (warp 0) ----
    if (tid < 32) {
        int lane = tid;
        int carry = 0;
        #pragma unroll
        for (int base = 0; base < NCELL + 31; base += 32) {
            int c = base + lane;
            int v = (c < NCELL) ? cnt[c] : 0;
            int s = v;
            #pragma unroll
            for (int off = 1; off < 32; off <<= 1) {
                int n = __shfl_up_sync(0xffffffffu, s, off);
                if (lane >= off) s += n;
            }
            int excl = s - v + carry;
            if (c < NCELL) { start[c] = excl; ofs[c] = excl; }
            carry += __shfl_sync(0xffffffffu, s, 31);
            if (base + 32 >= NCELL && lane == 0) start[NCELL] = carry;
        }
    }
    __syncthreads();

    // ---- phase 3: scatter scaled points into sorted order ----
    {
        int slot = atomicAdd(&ofs[pcell], 1);
        pts[slot] = make_float4(pxv.x * u0, pxv.y * u0, pyv, 0.0f);
    }
    __syncthreads();

    // ---- phase 4: query — 4 consecutive lanes cooperate per target ----
    const float stx = tv.x * u0;
    const float sty = tv.y * u0;

    const int cx = cell_of(tv.x);
    const int cy = cell_of(tv.y);
    const int cx0 = max(0, cx - nb), cx1 = min(GRID - 1, cx + nb);
    const int cy0 = max(0, cy - nb), cy1 = min(GRID - 1, cy + nb);

    float acc0 = 0.0f;   // density channel
    float acc1 = 0.0f;   // conv channel

    if (equal_sig) {
        for (int ry = cy0; ry <= cy1; ++ry) {
            int js = start[ry * GRID + cx0];
            int je = start[ry * GRID + cx1 + 1];
            #pragma unroll 2
            for (int j = js + sub; j < je; j += NSUB) {
                float4 p = pts[j];                 // lanes of a group: 64B contiguous
                float dx = p.x - stx;
                float dy = p.y - sty;
                float d  = fmaf(dy, dy, dx * dx);
                float e0 = ex2_approx(-d);
                acc0 += e0;
                acc1 = fmaf(p.z, e0, acc1);
            }
        }
    } else {
        for (int ry = cy0; ry <= cy1; ++ry) {
            int js = start[ry * GRID + cx0];
            int je = start[ry * GRID + cx1 + 1];
            #pragma unroll 2
            for (int j = js + sub; j < je; j += NSUB) {
                float4 p = pts[j];
                float dx = p.x - stx;
                float dy = p.y - sty;
                float d  = fmaf(dy, dy, dx * dx);
                float e0 = ex2_approx(-d);
                float e1 = ex2_approx(-d * ratio);
                acc0 += e0;
                acc1 = fmaf(p.z, e1, acc1);
            }
        }
    }

    // ---- in-warp reduction over the 4 sub-lanes (width-4 butterflies) ----
    acc0 += __shfl_xor_sync(0xffffffffu, acc0, 1, 4);
    acc1 += __shfl_xor_sync(0xffffffffu, acc1, 1, 4);
    acc0 += __shfl_xor_sync(0xffffffffu, acc0, 2, 4);
    acc1 += __shfl_xor_sync(0xffffffffu, acc1, 2, 4);

    if (sub == 0) {
        dens_s[ml] = acc0;
        q_s[ml]    = acc1 / (acc0 + 1e-8f);
    }
    __syncthreads();

    // ---- phase 5: epilogue: out[b, m, o] = dens*W[o,0] + q*W[o,1] + b[o] ----
    float4* __restrict__ ob =
        (float4*)(out + ((size_t)b * N_OUT + (size_t)blockIdx.x * M_PER_BLOCK) * OC);

    #pragma unroll
    for (int i = tid; i < M_PER_BLOCK * OC / 4; i += THREADS) {
        int m_local = i >> 4;          // 16 float4 per m-row
        int o0      = (i & 15) * 4;
        float f0 = dens_s[m_local];
        float f1 = q_s[m_local];
        float4 v;
        v.x = fmaf(f0, Ws[(o0 + 0) * 2], fmaf(f1, Ws[(o0 + 0) * 2 + 1], bs[o0 + 0]));
        v.y = fmaf(f0, Ws[(o0 + 1) * 2], fmaf(f1, Ws[(o0 + 1) * 2 + 1], bs[o0 + 1]));
        v.z = fmaf(f0, Ws[(o0 + 2) * 2], fmaf(f1, Ws[(o0 + 2) * 2 + 1], bs[o0 + 2]));
        v.w = fmaf(f0, Ws[(o0 + 3) * 2], fmaf(f1, Ws[(o0 + 3) * 2 + 1], bs[o0 + 3]));
        ob[i] = v;
    }
}

extern "C" void kernel_launch(void* const* d_in, const int* in_sizes, int n_in,
                              void* d_out, int out_size)
{
    const float* x     = (const float*)d_in[0];
    const float* y     = (const float*)d_in[1];
    const float* t     = (const float*)d_in[2];
    const float* sigma = (const float*)d_in[3];
    const float* W     = (const float*)d_in[4];
    const float* bias  = (const float*)d_in[5];
    float* out = (float*)d_out;

    dim3 grid(N_OUT / M_PER_BLOCK, BATCH);   // 16 x 8 = 128 blocks, single wave
    conv_deepset_kernel<<<grid, THREADS>>>(x, y, t, sigma, W, bias, out);
}